// round 16
// baseline (speedup 1.0000x reference)
#include <cuda_runtime.h>
#include <cstdint>

// ============================================================================
// TiLinear hybrid v11: R15 + tensor-ring producer moved OFF the tensor warps.
//   warps 0-7  : dp4a k [17,32); warp0-lane0 drives the dp4a ring; warp1-lane0
//                drives the TENSOR ring (paced 1 fill per k-iter + catch-up
//                before each pfull wait); tile tail: combine + |max| + STG C.
//   warps 8-15 : mma.sync IMMA k [0,17); pure consume (full-wait/ldmatrix/mma/
//                empty-arrive) -> park partial in smem.
// 3 launches: pack (also zeroes g_max), gemm, epilogue (writes exp tail).
// ============================================================================

#define M_DIM 8192
#define N_DIM 4096
#define K_DIM 4096
#define BITWIDTH 7

#define NTILES_TOTAL 2048
#define GRID_P 148

#define KTILES 32
#define NKT_T 17
#define NKT_D (KTILES - NKT_T)   // 15
#define TILE_BYTES 16384
#define STAGE_BYTES 32768
#define NST_T 3
#define NST_D 2
#define PB_STRIDE 130
#define TPOOL_OFF 0
#define DPOOL_OFF (NST_T * STAGE_BYTES)                  // 98304
#define PART_OFF  (DPOOL_OFF + NST_D * STAGE_BYTES)      // 163840
#define PART_BYTES (128 * PB_STRIDE * 4)                 // 66560
#define CTRL_OFF  (PART_OFF + PART_BYTES)                // 230400
#define SMEM_DYN  (CTRL_OFF + 128)                       // 230528

__device__ __align__(128) int8_t g_A8[(size_t)M_DIM * K_DIM];   // 32 MB
__device__ __align__(128) int8_t g_B8[(size_t)N_DIM * K_DIM];   // 16 MB
__device__ __align__(16)  int    g_C[(size_t)M_DIM * N_DIM];    // 128 MB
__device__ int g_max;

// ----------------------------------------------------------------------------
__global__ void __launch_bounds__(256) pack_kernel(const int* __restrict__ srcA,
                                                   const int* __restrict__ srcB) {
    if (blockIdx.x == 0 && threadIdx.x == 0) g_max = 0;
    if (blockIdx.x < 8192) {
        unsigned i = blockIdx.x * 256u + threadIdx.x;
        unsigned lc = i & 7u;
        unsigned m  = (i >> 3) & 8191u;
        unsigned kt = i >> 16;
        const int4* s = (const int4*)(srcA + (size_t)m * K_DIM + kt * 128 + lc * 16);
        uint32_t w[4];
#pragma unroll
        for (int j = 0; j < 4; ++j) {
            int4 v = s[j];
            w[j] = (uint32_t)(v.x & 0xff) | ((uint32_t)(v.y & 0xff) << 8) |
                   ((uint32_t)(v.z & 0xff) << 16) | ((uint32_t)(v.w & 0xff) << 24);
        }
        unsigned lr = m & 127u;
        size_t base = (size_t)(kt * 64 + (m >> 7)) * TILE_BYTES;
        size_t off  = base + lr * 128 + (((lc ^ lr) & 7u) << 4);
        *(uint4*)(g_A8 + off) = make_uint4(w[0], w[1], w[2], w[3]);
    } else {
        unsigned i = (blockIdx.x - 8192) * 256u + threadIdx.x;
        unsigned lc = i & 7u;
        unsigned n  = (i >> 3) & 4095u;
        unsigned kt = i >> 15;
        const int4* s = (const int4*)(srcB + (size_t)n * K_DIM + kt * 128 + lc * 16);
        uint32_t w[4];
#pragma unroll
        for (int j = 0; j < 4; ++j) {
            int4 v = s[j];
            w[j] = (uint32_t)(v.x & 0xff) | ((uint32_t)(v.y & 0xff) << 8) |
                   ((uint32_t)(v.z & 0xff) << 16) | ((uint32_t)(v.w & 0xff) << 24);
        }
        unsigned lr = n & 127u;
        size_t base = (size_t)(kt * 32 + (n >> 7)) * TILE_BYTES;
        size_t off  = base + lr * 128 + (((lc ^ lr) & 7u) << 4);
        *(uint4*)(g_B8 + off) = make_uint4(w[0], w[1], w[2], w[3]);
    }
}

// ----------------------------------------------------------------------------
__device__ __forceinline__ void mbar_init(uint32_t a, uint32_t cnt) {
    asm volatile("mbarrier.init.shared.b64 [%0], %1;" :: "r"(a), "r"(cnt) : "memory");
}
__device__ __forceinline__ void mbar_expect_tx(uint32_t a, uint32_t bytes) {
    asm volatile("mbarrier.arrive.expect_tx.shared.b64 _, [%0], %1;"
                 :: "r"(a), "r"(bytes) : "memory");
}
__device__ __forceinline__ void mbar_arrive(uint32_t a) {
    asm volatile("mbarrier.arrive.shared.b64 _, [%0];" :: "r"(a) : "memory");
}
__device__ __forceinline__ void mbar_wait(uint32_t a, uint32_t parity) {
    asm volatile(
        "{\n\t.reg .pred P;\n\t"
        "WAIT_%=:\n\t"
        "mbarrier.try_wait.parity.acquire.cta.shared::cta.b64 P, [%0], %1, 0x989680;\n\t"
        "@P bra.uni DONE_%=;\n\t"
        "bra.uni WAIT_%=;\n\t"
        "DONE_%=:\n\t}"
        :: "r"(a), "r"(parity) : "memory");
}
__device__ __forceinline__ void bulk_g2s(uint32_t dst, const void* src,
                                         uint32_t bytes, uint32_t mbar) {
    asm volatile(
        "cp.async.bulk.shared::cluster.global.mbarrier::complete_tx::bytes "
        "[%0], [%1], %2, [%3];"
        :: "r"(dst), "l"(src), "r"(bytes), "r"(mbar) : "memory");
}
__device__ __forceinline__ uint32_t swz_off(uint32_t row, uint32_t chunk) {
    return row * 128u + (((chunk ^ row) & 7u) << 4);
}
__device__ __forceinline__ void fill_blocks(uint32_t dst, uint32_t mbar,
                                            int ablk, int bblk) {
    mbar_expect_tx(mbar, STAGE_BYTES);
    bulk_g2s(dst, g_A8 + (size_t)ablk * TILE_BYTES, TILE_BYTES, mbar);
    bulk_g2s(dst + TILE_BYTES, g_B8 + (size_t)bblk * TILE_BYTES, TILE_BYTES, mbar);
}

// ----------------------------------------------------------------------------
__global__ void __launch_bounds__(512, 1) gemm_persist_kernel() {
    extern __shared__ __align__(1024) int8_t smem[];
    const int tid  = threadIdx.x;
    const int lane = tid & 31;
    const int warp = tid >> 5;
    const int bid  = blockIdx.x;
    const int ntiles = (NTILES_TOTAL - 1 - bid) / GRID_P + 1;
    const uint32_t sbase = (uint32_t)__cvta_generic_to_shared(smem);
    const uint32_t mbT   = sbase + CTRL_OFF;
    const uint32_t mbD   = sbase + CTRL_OFF + 48;
    const uint32_t pfull = sbase + CTRL_OFF + 80;   // tensor -> dp4a
    const uint32_t pfree = sbase + CTRL_OFF + 88;   // dp4a -> tensor
    int* pbuf = (int*)(smem + PART_OFF);

    if (tid == 0) {
#pragma unroll
        for (int s = 0; s < NST_T; ++s) {
            mbar_init(mbT + s * 16 + 0, 1);
            mbar_init(mbT + s * 16 + 8, 8);
        }
#pragma unroll
        for (int s = 0; s < NST_D; ++s) {
            mbar_init(mbD + s * 16 + 0, 1);
            mbar_init(mbD + s * 16 + 8, 8);
        }
        mbar_init(pfull, 8);
        mbar_init(pfree, 8);
        asm volatile("fence.mbarrier_init.release.cluster;" ::: "memory");
    }
    __syncthreads();

    if (warp >= 8) {
        // ========== TENSOR GROUP: warps 8-15, k [0,17), PURE CONSUMER ==========
        const int tw = warp - 8;
        const int wm = tw >> 2, wn = tw & 3;
        int cs = 0, cp = 0;
        int pt = 1;                     // pfree wait parity

        for (int li = 0; li < ntiles; ++li) {
            int acc[4][4][4];
#pragma unroll
            for (int a = 0; a < 4; ++a)
#pragma unroll
                for (int b = 0; b < 4; ++b)
#pragma unroll
                    for (int c = 0; c < 4; ++c) acc[a][b][c] = 0;

#pragma unroll 1
            for (int k = 0; k < NKT_T; ++k) {
                mbar_wait(mbT + cs * 16, cp);

                const int8_t* sa = smem + TPOOL_OFF + cs * STAGE_BYTES;
                const int8_t* sb = sa + TILE_BYTES;
#pragma unroll
                for (int ks = 0; ks < 4; ++ks) {
                    uint32_t afr[4][4];
#pragma unroll
                    for (int mi = 0; mi < 4; ++mi) {
                        int r = wm * 64 + mi * 16 + (lane & 15);
                        int c = ks * 2 + (lane >> 4);
                        uint32_t addr =
                            (uint32_t)__cvta_generic_to_shared(sa + swz_off(r, c));
                        asm volatile(
                            "ldmatrix.sync.aligned.m8n8.x4.shared.b16 "
                            "{%0,%1,%2,%3}, [%4];\n"
                            : "=r"(afr[mi][0]), "=r"(afr[mi][1]),
                              "=r"(afr[mi][2]), "=r"(afr[mi][3])
                            : "r"(addr));
                    }
                    uint32_t bfr[4][2];
#pragma unroll
                    for (int ni = 0; ni < 4; ++ni) {
                        int r = wn * 32 + ni * 8 + (lane & 7);
                        int c = ks * 2 + ((lane >> 3) & 1);
                        uint32_t addr =
                            (uint32_t)__cvta_generic_to_shared(sb + swz_off(r, c));
                        asm volatile(
                            "ldmatrix.sync.aligned.m8n8.x2.shared.b16 {%0,%1}, [%2];\n"
                            : "=r"(bfr[ni][0]), "=r"(bfr[ni][1])
                            : "r"(addr));
                    }
#pragma unroll
                    for (int mi = 0; mi < 4; ++mi)
#pragma unroll
                        for (int ni = 0; ni < 4; ++ni) {
                            asm volatile(
                                "mma.sync.aligned.m16n8k32.row.col.s32.s8.s8.s32 "
                                "{%0,%1,%2,%3}, {%4,%5,%6,%7}, {%8,%9}, {%0,%1,%2,%3};\n"
                                : "+r"(acc[mi][ni][0]), "+r"(acc[mi][ni][1]),
                                  "+r"(acc[mi][ni][2]), "+r"(acc[mi][ni][3])
                                : "r"(afr[mi][0]), "r"(afr[mi][1]),
                                  "r"(afr[mi][2]), "r"(afr[mi][3]),
                                  "r"(bfr[ni][0]), "r"(bfr[ni][1]));
                        }
                }
                __syncwarp();
                if (lane == 0) mbar_arrive(mbT + cs * 16 + 8);
                if (++cs == NST_T) { cs = 0; cp ^= 1; }
            }

            // park partial in smem
            mbar_wait(pfree, pt);
            pt ^= 1;
#pragma unroll
            for (int mi = 0; mi < 4; ++mi)
#pragma unroll
                for (int ni = 0; ni < 4; ++ni) {
                    int r = wm * 64 + mi * 16 + (lane >> 2);
                    int c = wn * 32 + ni * 8 + (lane & 3) * 2;
                    *(int2*)&pbuf[r * PB_STRIDE + c] =
                        make_int2(acc[mi][ni][0], acc[mi][ni][1]);
                    *(int2*)&pbuf[(r + 8) * PB_STRIDE + c] =
                        make_int2(acc[mi][ni][2], acc[mi][ni][3]);
                }
            __syncwarp();
            if (lane == 0) mbar_arrive(pfull);
        }
    } else {
        // ========== DP4A GROUP: warps 0-7, k [17,32) + BOTH ring producers ======
        const int wd = warp;
        const int mg = lane >> 4;
        const int ng = lane & 15;
        const int rowA0 = 16 * wd + 8 * mg;
        const int totalD = ntiles * NKT_D;
        const int totalT = ntiles * NKT_T;
        int cs = 0, cp = 0;
        int ps = 0, pp = 1;             // dp4a ring producer (tid 0)
        int psT = 0, ppT = 1, nfT = 0;  // tensor ring producer (tid 32)
        int pd = 0;
        int lmax = 0;

        auto d_fill = [&](int f) {
            int li = f / NKT_D;
            int kd = f - li * NKT_D;
            int tile = bid + li * GRID_P;
            mbar_wait(mbD + ps * 16 + 8, pp);
            fill_blocks(sbase + DPOOL_OFF + ps * STAGE_BYTES, mbD + ps * 16,
                        (NKT_T + kd) * 64 + (tile >> 5),
                        (NKT_T + kd) * 32 + (tile & 31));
            if (++ps == NST_D) { ps = 0; pp ^= 1; }
        };
        auto t_fill = [&]() {
            int f  = nfT++;
            int li = f / NKT_T;
            int kt = f - li * NKT_T;
            int tile = bid + li * GRID_P;
            mbar_wait(mbT + psT * 16 + 8, ppT);
            fill_blocks(sbase + TPOOL_OFF + psT * STAGE_BYTES, mbT + psT * 16,
                        kt * 64 + (tile >> 5), kt * 32 + (tile & 31));
            if (++psT == NST_T) { psT = 0; ppT ^= 1; }
        };

        if (tid == 0 && totalD > 0) d_fill(0);
        if (tid == 32) {
            if (totalT > 0) t_fill();
            if (totalT > 1) t_fill();
        }

        for (int li = 0; li < ntiles; ++li) {
            const int tile = bid + li * GRID_P;
            const int m0 = (tile >> 5) * 128;
            const int n0 = (tile & 31) * 128;
            const int tcap = (li + 1) * NKT_T + 2 < totalT
                                 ? (li + 1) * NKT_T + 2 : totalT;

            int accD[64];
#pragma unroll
            for (int j = 0; j < 64; ++j) accD[j] = 0;

#pragma unroll 1
            for (int k = 0; k < NKT_D; ++k) {
                if (tid == 0) {
                    int f = li * NKT_D + k + 1;
                    if (f < totalD) d_fill(f);
                }
                if (tid == 32 && nfT < tcap) t_fill();   // paced: 1 per k-iter
                mbar_wait(mbD + cs * 16, cp);

                const int8_t* sa = smem + DPOOL_OFF + cs * STAGE_BYTES;
                const int8_t* sb = sa + TILE_BYTES;
#pragma unroll 1
                for (int cc = 0; cc < 8; ++cc) {
                    int4 a[8];
#pragma unroll
                    for (int i = 0; i < 8; ++i) {
                        int r = rowA0 + i;
                        a[i] = *(const int4*)(sa + r * 128 + (((cc ^ r) & 7) << 4));
                    }
                    const int boff = ((cc ^ ng) & 7) << 4;
                    int4 b = *(const int4*)(sb + ng * 128 + boff);
#pragma unroll
                    for (int j = 0; j < 8; ++j) {
                        int4 bn;
                        if (j < 7)
                            bn = *(const int4*)(sb + (16 * (j + 1) + ng) * 128 + boff);
#pragma unroll
                        for (int i = 0; i < 8; ++i) {
                            int t = __dp4a(a[i].x, b.x, accD[i * 8 + j]);
                            t = __dp4a(a[i].y, b.y, t);
                            t = __dp4a(a[i].z, b.z, t);
                            accD[i * 8 + j] = __dp4a(a[i].w, b.w, t);
                        }
                        if (j < 7) b = bn;
                    }
                }
                __syncwarp();
                if (lane == 0) mbar_arrive(mbD + cs * 16 + 8);
                if (++cs == NST_D) { cs = 0; cp ^= 1; }
            }

            // catch-up: guarantee tensor can finish tile li (+2 prime fills)
            if (tid == 32) {
                while (nfT < tcap) t_fill();
            }

            // combine in the slack: read tensor partial, add, max, store C
            mbar_wait(pfull, pd);
            pd ^= 1;
#pragma unroll
            for (int i = 0; i < 8; ++i) {
                int r = rowA0 + i;
                const int* prow = pbuf + r * PB_STRIDE;
                int* dst = g_C + (size_t)(m0 + r) * N_DIM + n0;
#pragma unroll
                for (int j = 0; j < 8; ++j) {
                    int v = prow[16 * j + ng] + accD[i * 8 + j];
                    lmax = max(lmax, abs(v));
                    dst[16 * j + ng] = v;
                }
            }
            __syncwarp();
            if (lane == 0) mbar_arrive(pfree);
        }

#pragma unroll
        for (int o = 16; o > 0; o >>= 1)
            lmax = max(lmax, __shfl_xor_sync(0xffffffffu, lmax, o));
        if (lane == 0) atomicMax(&g_max, lmax);
    }
}

// ----------------------------------------------------------------------------
__device__ __forceinline__ int compute_eff() {
    int m = g_max;
    if (m == 0) return 0;
    float mf = (float)m;
    unsigned bits = __float_as_uint(mf);
    int e  = (int)((bits >> 23) & 0xff) - 127;
    int bw = e + ((bits & 0x7fffffu) ? 1 : 0);
    int shift = bw - BITWIDTH;
    return shift > 1 ? shift : (shift == 1 ? 2 : 0);
}

__device__ __forceinline__ int psto_one(int x, int s) {
    int rt   = x >> s;
    int prob = x & ((1 << s) - 1);
    int h    = s >> 1;
    int qp   = prob >> h;
    int prn  = prob & ((1 << h) - 1);
    if (s & 1) prn <<= 1;
    int sgn = (x > 0) - (x < 0);
    int dec = (qp <= prn) ? 0 : sgn;
    int o = rt + dec;
    o = o > 127 ? 127 : (o < -127 ? -127 : o);
    return o;
}

__global__ void __launch_bounds__(256) epilogue_kernel(
    float* __restrict__ out, const int* __restrict__ e1,
    const int* __restrict__ e2, long long out_size) {
    const int eff = compute_eff();
    size_t i = (size_t)blockIdx.x * blockDim.x + threadIdx.x;
    int4 v = ((const int4*)g_C)[i];
    float4 o;
    if (eff > 0) {
        o.x = (float)psto_one(v.x, eff);
        o.y = (float)psto_one(v.y, eff);
        o.z = (float)psto_one(v.z, eff);
        o.w = (float)psto_one(v.w, eff);
    } else {
        o.x = (float)(int8_t)(v.x);
        o.y = (float)(int8_t)(v.y);
        o.z = (float)(int8_t)(v.z);
        o.w = (float)(int8_t)(v.w);
    }
    ((float4*)out)[i] = o;

    if (blockIdx.x == 0) {
        long long total = (long long)M_DIM * N_DIM;
        int8_t ev = (int8_t)(e1[0] + e2[0] + eff);
        for (long long t = total + threadIdx.x; t < out_size; t += 256)
            out[t] = (float)ev;
    }
}

// ----------------------------------------------------------------------------
extern "C" void kernel_launch(void* const* d_in, const int* in_sizes, int n_in,
                              void* d_out, int out_size) {
    const int* act   = (const int*)d_in[0];
    const int* expin = (const int*)d_in[1];
    const int* wgt   = (const int*)d_in[2];
    const int* wexp  = (const int*)d_in[3];
    float* out = (float*)d_out;
    (void)in_sizes; (void)n_in;

    cudaFuncSetAttribute(gemm_persist_kernel,
                         cudaFuncAttributeMaxDynamicSharedMemorySize, SMEM_DYN);

    pack_kernel<<<12288, 256>>>(act, wgt);
    gemm_persist_kernel<<<GRID_P, 512, SMEM_DYN>>>();

    long long total = (long long)M_DIM * N_DIM;           // 33554432
    epilogue_kernel<<<(int)(total / 4 / 256), 256>>>(out, expin, wexp,
                                                     (long long)out_size);
}

// round 17
// speedup vs baseline: 1.0245x; 1.0245x over previous
#include <cuda_runtime.h>
#include <cstdint>

// ============================================================================
// TiLinear hybrid v12 = R15 (best structure) + software-pipelined tensor ks
// body: B frags first, then per-mi "load afr(mi+1) || MMA(mi)" ping-pong.
// asm volatile order == issue order, so this source order IS the pipeline.
//   warps 0-7  : dp4a k [17,32), 2-stage ring (+1 la); tail: combine+|max|+STG
//   warps 8-15 : IMMA k [0,17), 3-stage ring (+2 la, producer tid 256);
//                tail: park partial in smem
// 3 launches: pack (zeroes g_max), gemm, epilogue (exp tail in block 0).
// ============================================================================

#define M_DIM 8192
#define N_DIM 4096
#define K_DIM 4096
#define BITWIDTH 7

#define NTILES_TOTAL 2048
#define GRID_P 148

#define KTILES 32
#define NKT_T 17
#define NKT_D (KTILES - NKT_T)   // 15
#define TILE_BYTES 16384
#define STAGE_BYTES 32768
#define NST_T 3
#define NST_D 2
#define PB_STRIDE 130
#define TPOOL_OFF 0
#define DPOOL_OFF (NST_T * STAGE_BYTES)                  // 98304
#define PART_OFF  (DPOOL_OFF + NST_D * STAGE_BYTES)      // 163840
#define PART_BYTES (128 * PB_STRIDE * 4)                 // 66560
#define CTRL_OFF  (PART_OFF + PART_BYTES)                // 230400
#define SMEM_DYN  (CTRL_OFF + 128)                       // 230528

__device__ __align__(128) int8_t g_A8[(size_t)M_DIM * K_DIM];   // 32 MB
__device__ __align__(128) int8_t g_B8[(size_t)N_DIM * K_DIM];   // 16 MB
__device__ __align__(16)  int    g_C[(size_t)M_DIM * N_DIM];    // 128 MB
__device__ int g_max;

// ----------------------------------------------------------------------------
__global__ void __launch_bounds__(256) pack_kernel(const int* __restrict__ srcA,
                                                   const int* __restrict__ srcB) {
    if (blockIdx.x == 0 && threadIdx.x == 0) g_max = 0;
    if (blockIdx.x < 8192) {
        unsigned i = blockIdx.x * 256u + threadIdx.x;
        unsigned lc = i & 7u;
        unsigned m  = (i >> 3) & 8191u;
        unsigned kt = i >> 16;
        const int4* s = (const int4*)(srcA + (size_t)m * K_DIM + kt * 128 + lc * 16);
        uint32_t w[4];
#pragma unroll
        for (int j = 0; j < 4; ++j) {
            int4 v = s[j];
            w[j] = (uint32_t)(v.x & 0xff) | ((uint32_t)(v.y & 0xff) << 8) |
                   ((uint32_t)(v.z & 0xff) << 16) | ((uint32_t)(v.w & 0xff) << 24);
        }
        unsigned lr = m & 127u;
        size_t base = (size_t)(kt * 64 + (m >> 7)) * TILE_BYTES;
        size_t off  = base + lr * 128 + (((lc ^ lr) & 7u) << 4);
        *(uint4*)(g_A8 + off) = make_uint4(w[0], w[1], w[2], w[3]);
    } else {
        unsigned i = (blockIdx.x - 8192) * 256u + threadIdx.x;
        unsigned lc = i & 7u;
        unsigned n  = (i >> 3) & 4095u;
        unsigned kt = i >> 15;
        const int4* s = (const int4*)(srcB + (size_t)n * K_DIM + kt * 128 + lc * 16);
        uint32_t w[4];
#pragma unroll
        for (int j = 0; j < 4; ++j) {
            int4 v = s[j];
            w[j] = (uint32_t)(v.x & 0xff) | ((uint32_t)(v.y & 0xff) << 8) |
                   ((uint32_t)(v.z & 0xff) << 16) | ((uint32_t)(v.w & 0xff) << 24);
        }
        unsigned lr = n & 127u;
        size_t base = (size_t)(kt * 32 + (n >> 7)) * TILE_BYTES;
        size_t off  = base + lr * 128 + (((lc ^ lr) & 7u) << 4);
        *(uint4*)(g_B8 + off) = make_uint4(w[0], w[1], w[2], w[3]);
    }
}

// ----------------------------------------------------------------------------
__device__ __forceinline__ void mbar_init(uint32_t a, uint32_t cnt) {
    asm volatile("mbarrier.init.shared.b64 [%0], %1;" :: "r"(a), "r"(cnt) : "memory");
}
__device__ __forceinline__ void mbar_expect_tx(uint32_t a, uint32_t bytes) {
    asm volatile("mbarrier.arrive.expect_tx.shared.b64 _, [%0], %1;"
                 :: "r"(a), "r"(bytes) : "memory");
}
__device__ __forceinline__ void mbar_arrive(uint32_t a) {
    asm volatile("mbarrier.arrive.shared.b64 _, [%0];" :: "r"(a) : "memory");
}
__device__ __forceinline__ void mbar_wait(uint32_t a, uint32_t parity) {
    asm volatile(
        "{\n\t.reg .pred P;\n\t"
        "WAIT_%=:\n\t"
        "mbarrier.try_wait.parity.acquire.cta.shared::cta.b64 P, [%0], %1, 0x989680;\n\t"
        "@P bra.uni DONE_%=;\n\t"
        "bra.uni WAIT_%=;\n\t"
        "DONE_%=:\n\t}"
        :: "r"(a), "r"(parity) : "memory");
}
__device__ __forceinline__ void bulk_g2s(uint32_t dst, const void* src,
                                         uint32_t bytes, uint32_t mbar) {
    asm volatile(
        "cp.async.bulk.shared::cluster.global.mbarrier::complete_tx::bytes "
        "[%0], [%1], %2, [%3];"
        :: "r"(dst), "l"(src), "r"(bytes), "r"(mbar) : "memory");
}
__device__ __forceinline__ uint32_t swz_off(uint32_t row, uint32_t chunk) {
    return row * 128u + (((chunk ^ row) & 7u) << 4);
}
__device__ __forceinline__ void fill_blocks(uint32_t dst, uint32_t mbar,
                                            int ablk, int bblk) {
    mbar_expect_tx(mbar, STAGE_BYTES);
    bulk_g2s(dst, g_A8 + (size_t)ablk * TILE_BYTES, TILE_BYTES, mbar);
    bulk_g2s(dst + TILE_BYTES, g_B8 + (size_t)bblk * TILE_BYTES, TILE_BYTES, mbar);
}
__device__ __forceinline__ void ldsm_x4(uint32_t addr, uint32_t* r) {
    asm volatile(
        "ldmatrix.sync.aligned.m8n8.x4.shared.b16 {%0,%1,%2,%3}, [%4];\n"
        : "=r"(r[0]), "=r"(r[1]), "=r"(r[2]), "=r"(r[3]) : "r"(addr));
}

// ----------------------------------------------------------------------------
__global__ void __launch_bounds__(512, 1) gemm_persist_kernel() {
    extern __shared__ __align__(1024) int8_t smem[];
    const int tid  = threadIdx.x;
    const int lane = tid & 31;
    const int warp = tid >> 5;
    const int bid  = blockIdx.x;
    const int ntiles = (NTILES_TOTAL - 1 - bid) / GRID_P + 1;
    const uint32_t sbase = (uint32_t)__cvta_generic_to_shared(smem);
    const uint32_t mbT   = sbase + CTRL_OFF;
    const uint32_t mbD   = sbase + CTRL_OFF + 48;
    const uint32_t pfull = sbase + CTRL_OFF + 80;   // tensor -> dp4a
    const uint32_t pfree = sbase + CTRL_OFF + 88;   // dp4a -> tensor
    int* pbuf = (int*)(smem + PART_OFF);

    if (tid == 0) {
#pragma unroll
        for (int s = 0; s < NST_T; ++s) {
            mbar_init(mbT + s * 16 + 0, 1);
            mbar_init(mbT + s * 16 + 8, 8);
        }
#pragma unroll
        for (int s = 0; s < NST_D; ++s) {
            mbar_init(mbD + s * 16 + 0, 1);
            mbar_init(mbD + s * 16 + 8, 8);
        }
        mbar_init(pfull, 8);
        mbar_init(pfree, 8);
        asm volatile("fence.mbarrier_init.release.cluster;" ::: "memory");
    }
    __syncthreads();

    if (warp >= 8) {
        // ================= TENSOR GROUP: warps 8-15, k [0,17) =================
        const int tw = warp - 8;
        const int wm = tw >> 2, wn = tw & 3;
        const int total = ntiles * NKT_T;
        int cs = 0, cp = 0;
        int ps = 0, pp = 1;
        int pt = 1;

        auto t_fill = [&](int f) {
            int li = f / NKT_T;
            int kt = f - li * NKT_T;
            int tile = bid + li * GRID_P;
            mbar_wait(mbT + ps * 16 + 8, pp);
            fill_blocks(sbase + TPOOL_OFF + ps * STAGE_BYTES, mbT + ps * 16,
                        kt * 64 + (tile >> 5), kt * 32 + (tile & 31));
            if (++ps == NST_T) { ps = 0; pp ^= 1; }
        };

        if (tid == 256) {
            if (total > 0) t_fill(0);
            if (total > 1) t_fill(1);
        }

        for (int li = 0; li < ntiles; ++li) {
            int acc[4][4][4];
#pragma unroll
            for (int a = 0; a < 4; ++a)
#pragma unroll
                for (int b = 0; b < 4; ++b)
#pragma unroll
                    for (int c = 0; c < 4; ++c) acc[a][b][c] = 0;

#pragma unroll 1
            for (int k = 0; k < NKT_T; ++k) {
                if (tid == 256) {
                    int f = li * NKT_T + k + 2;
                    if (f < total) t_fill(f);
                }
                mbar_wait(mbT + cs * 16, cp);

                const int8_t* sa = smem + TPOOL_OFF + cs * STAGE_BYTES;
                const int8_t* sb = sa + TILE_BYTES;
#pragma unroll
                for (int ks = 0; ks < 4; ++ks) {
                    // 1) B fragments first (their latency hides under prior MMAs)
                    uint32_t bfr[4][2];
#pragma unroll
                    for (int ni = 0; ni < 4; ++ni) {
                        int r = wn * 32 + ni * 8 + (lane & 7);
                        int c = ks * 2 + ((lane >> 3) & 1);
                        uint32_t addr =
                            (uint32_t)__cvta_generic_to_shared(sb + swz_off(r, c));
                        asm volatile(
                            "ldmatrix.sync.aligned.m8n8.x2.shared.b16 {%0,%1}, [%2];\n"
                            : "=r"(bfr[ni][0]), "=r"(bfr[ni][1])
                            : "r"(addr));
                    }
                    // 2) ping-pong A fragments: load afr(mi+1) BEFORE MMAs(mi)
                    uint32_t afr[2][4];
                    {
                        int r = wm * 64 + 0 * 16 + (lane & 15);
                        int c = ks * 2 + (lane >> 4);
                        ldsm_x4((uint32_t)__cvta_generic_to_shared(
                                    sa + swz_off(r, c)), afr[0]);
                    }
#pragma unroll
                    for (int mi = 0; mi < 4; ++mi) {
                        const int cur = mi & 1;
                        if (mi < 3) {
                            int r = wm * 64 + (mi + 1) * 16 + (lane & 15);
                            int c = ks * 2 + (lane >> 4);
                            ldsm_x4((uint32_t)__cvta_generic_to_shared(
                                        sa + swz_off(r, c)), afr[cur ^ 1]);
                        }
#pragma unroll
                        for (int ni = 0; ni < 4; ++ni) {
                            asm volatile(
                                "mma.sync.aligned.m16n8k32.row.col.s32.s8.s8.s32 "
                                "{%0,%1,%2,%3}, {%4,%5,%6,%7}, {%8,%9}, {%0,%1,%2,%3};\n"
                                : "+r"(acc[mi][ni][0]), "+r"(acc[mi][ni][1]),
                                  "+r"(acc[mi][ni][2]), "+r"(acc[mi][ni][3])
                                : "r"(afr[cur][0]), "r"(afr[cur][1]),
                                  "r"(afr[cur][2]), "r"(afr[cur][3]),
                                  "r"(bfr[ni][0]), "r"(bfr[ni][1]));
                        }
                    }
                }
                __syncwarp();
                if (lane == 0) mbar_arrive(mbT + cs * 16 + 8);
                if (++cs == NST_T) { cs = 0; cp ^= 1; }
            }

            // minimal tail: park partial in smem
            mbar_wait(pfree, pt);
            pt ^= 1;
#pragma unroll
            for (int mi = 0; mi < 4; ++mi)
#pragma unroll
                for (int ni = 0; ni < 4; ++ni) {
                    int r = wm * 64 + mi * 16 + (lane >> 2);
                    int c = wn * 32 + ni * 8 + (lane & 3) * 2;
                    *(int2*)&pbuf[r * PB_STRIDE + c] =
                        make_int2(acc[mi][ni][0], acc[mi][ni][1]);
                    *(int2*)&pbuf[(r + 8) * PB_STRIDE + c] =
                        make_int2(acc[mi][ni][2], acc[mi][ni][3]);
                }
            __syncwarp();
            if (lane == 0) mbar_arrive(pfull);
        }
    } else {
        // ================= DP4A GROUP: warps 0-7, k [17,32) =================
        const int wd = warp;
        const int mg = lane >> 4;
        const int ng = lane & 15;
        const int rowA0 = 16 * wd + 8 * mg;
        const int total = ntiles * NKT_D;
        int cs = 0, cp = 0;
        int ps = 0, pp = 1;
        int pd = 0;
        int lmax = 0;

        auto d_fill = [&](int f) {
            int li = f / NKT_D;
            int kd = f - li * NKT_D;
            int tile = bid + li * GRID_P;
            mbar_wait(mbD + ps * 16 + 8, pp);
            fill_blocks(sbase + DPOOL_OFF + ps * STAGE_BYTES, mbD + ps * 16,
                        (NKT_T + kd) * 64 + (tile >> 5),
                        (NKT_T + kd) * 32 + (tile & 31));
            if (++ps == NST_D) { ps = 0; pp ^= 1; }
        };

        if (tid == 0 && total > 0) d_fill(0);

        for (int li = 0; li < ntiles; ++li) {
            const int tile = bid + li * GRID_P;
            const int m0 = (tile >> 5) * 128;
            const int n0 = (tile & 31) * 128;

            int accD[64];
#pragma unroll
            for (int j = 0; j < 64; ++j) accD[j] = 0;

#pragma unroll 1
            for (int k = 0; k < NKT_D; ++k) {
                if (tid == 0) {
                    int f = li * NKT_D + k + 1;
                    if (f < total) d_fill(f);
                }
                mbar_wait(mbD + cs * 16, cp);

                const int8_t* sa = smem + DPOOL_OFF + cs * STAGE_BYTES;
                const int8_t* sb = sa + TILE_BYTES;
#pragma unroll 1
                for (int cc = 0; cc < 8; ++cc) {
                    int4 a[8];
#pragma unroll
                    for (int i = 0; i < 8; ++i) {
                        int r = rowA0 + i;
                        a[i] = *(const int4*)(sa + r * 128 + (((cc ^ r) & 7) << 4));
                    }
                    const int boff = ((cc ^ ng) & 7) << 4;
                    int4 b = *(const int4*)(sb + ng * 128 + boff);
#pragma unroll
                    for (int j = 0; j < 8; ++j) {
                        int4 bn;
                        if (j < 7)
                            bn = *(const int4*)(sb + (16 * (j + 1) + ng) * 128 + boff);
#pragma unroll
                        for (int i = 0; i < 8; ++i) {
                            int t = __dp4a(a[i].x, b.x, accD[i * 8 + j]);
                            t = __dp4a(a[i].y, b.y, t);
                            t = __dp4a(a[i].z, b.z, t);
                            accD[i * 8 + j] = __dp4a(a[i].w, b.w, t);
                        }
                        if (j < 7) b = bn;
                    }
                }
                __syncwarp();
                if (lane == 0) mbar_arrive(mbD + cs * 16 + 8);
                if (++cs == NST_D) { cs = 0; cp ^= 1; }
            }

            // combine in the slack: read tensor partial, add, max, store C
            mbar_wait(pfull, pd);
            pd ^= 1;
#pragma unroll
            for (int i = 0; i < 8; ++i) {
                int r = rowA0 + i;
                const int* prow = pbuf + r * PB_STRIDE;
                int* dst = g_C + (size_t)(m0 + r) * N_DIM + n0;
#pragma unroll
                for (int j = 0; j < 8; ++j) {
                    int v = prow[16 * j + ng] + accD[i * 8 + j];
                    lmax = max(lmax, abs(v));
                    dst[16 * j + ng] = v;
                }
            }
            __syncwarp();
            if (lane == 0) mbar_arrive(pfree);
        }

#pragma unroll
        for (int o = 16; o > 0; o >>= 1)
            lmax = max(lmax, __shfl_xor_sync(0xffffffffu, lmax, o));
        if (lane == 0) atomicMax(&g_max, lmax);
    }
}

// ----------------------------------------------------------------------------
__device__ __forceinline__ int compute_eff() {
    int m = g_max;
    if (m == 0) return 0;
    float mf = (float)m;
    unsigned bits = __float_as_uint(mf);
    int e  = (int)((bits >> 23) & 0xff) - 127;
    int bw = e + ((bits & 0x7fffffu) ? 1 : 0);
    int shift = bw - BITWIDTH;
    return shift > 1 ? shift : (shift == 1 ? 2 : 0);
}

__device__ __forceinline__ int psto_one(int x, int s) {
    int rt   = x >> s;
    int prob = x & ((1 << s) - 1);
    int h    = s >> 1;
    int qp   = prob >> h;
    int prn  = prob & ((1 << h) - 1);
    if (s & 1) prn <<= 1;
    int sgn = (x > 0) - (x < 0);
    int dec = (qp <= prn) ? 0 : sgn;
    int o = rt + dec;
    o = o > 127 ? 127 : (o < -127 ? -127 : o);
    return o;
}

__global__ void __launch_bounds__(256) epilogue_kernel(
    float* __restrict__ out, const int* __restrict__ e1,
    const int* __restrict__ e2, long long out_size) {
    const int eff = compute_eff();
    size_t i = (size_t)blockIdx.x * blockDim.x + threadIdx.x;
    int4 v = ((const int4*)g_C)[i];
    float4 o;
    if (eff > 0) {
        o.x = (float)psto_one(v.x, eff);
        o.y = (float)psto_one(v.y, eff);
        o.z = (float)psto_one(v.z, eff);
        o.w = (float)psto_one(v.w, eff);
    } else {
        o.x = (float)(int8_t)(v.x);
        o.y = (float)(int8_t)(v.y);
        o.z = (float)(int8_t)(v.z);
        o.w = (float)(int8_t)(v.w);
    }
    ((float4*)out)[i] = o;

    if (blockIdx.x == 0) {
        long long total = (long long)M_DIM * N_DIM;
        int8_t ev = (int8_t)(e1[0] + e2[0] + eff);
        for (long long t = total + threadIdx.x; t < out_size; t += 256)
            out[t] = (float)ev;
    }
}

// ----------------------------------------------------------------------------
extern "C" void kernel_launch(void* const* d_in, const int* in_sizes, int n_in,
                              void* d_out, int out_size) {
    const int* act   = (const int*)d_in[0];
    const int* expin = (const int*)d_in[1];
    const int* wgt   = (const int*)d_in[2];
    const int* wexp  = (const int*)d_in[3];
    float* out = (float*)d_out;
    (void)in_sizes; (void)n_in;

    cudaFuncSetAttribute(gemm_persist_kernel,
                         cudaFuncAttributeMaxDynamicSharedMemorySize, SMEM_DYN);

    pack_kernel<<<12288, 256>>>(act, wgt);
    gemm_persist_kernel<<<GRID_P, 512, SMEM_DYN>>>();

    long long total = (long long)M_DIM * N_DIM;           // 33554432
    epilogue_kernel<<<(int)(total / 4 / 256), 256>>>(out, expin, wexp,
                                                     (long long)out_size);
}